// round 1
// baseline (speedup 1.0000x reference)
#include <cuda_runtime.h>
#include <cstdint>

// Problem constants
#define Bc   4
#define Cc   256
#define Hc   64
#define Wc   64
#define OCc  256
#define Kc   9          // 3x3 taps
#define Pc   4096       // Ho*Wo = 64*64
#define CKc  (Cc*Kc)    // 2304

// Scratch: cols[b][c*9+k][p]  (151 MB device global — allowed, no cudaMalloc)
__device__ float g_cols[(size_t)Bc * CKc * Pc];

// ---------------------------------------------------------------------------
// Stage 1: deformable im2col.  One thread per (b,k,p); loops over c.
// ---------------------------------------------------------------------------
__global__ __launch_bounds__(256) void dcn_im2col(
    const float* __restrict__ x,       // [B,C,H,W]
    const float* __restrict__ offset)  // [B,18,Ho,Wo]
{
    int tid = blockIdx.x * 256 + threadIdx.x;      // < B*K*P = 147456
    int p = tid & (Pc - 1);
    int k = (tid >> 12) % Kc;
    int b = tid / (Pc * Kc);

    int ho = p >> 6;
    int wo = p & 63;
    int ki = k / 3;
    int kj = k - 3 * ki;

    const float* offb = offset + ((size_t)b * 18) * Pc;
    float dy = offb[(2 * k    ) * Pc + p];
    float dx = offb[(2 * k + 1) * Pc + p];

    float ph = (float)(ho - 1 + ki) + dy;
    float pw = (float)(wo - 1 + kj) + dx;

    float h0f = floorf(ph);
    float w0f = floorf(pw);
    float lh = ph - h0f;
    float lw = pw - w0f;
    int h0 = (int)h0f;
    int w0 = (int)w0f;
    int h1 = h0 + 1;
    int w1 = w0 + 1;

    float vh0 = (h0 >= 0 && h0 < Hc) ? 1.f : 0.f;
    float vh1 = (h1 >= 0 && h1 < Hc) ? 1.f : 0.f;
    float vw0 = (w0 >= 0 && w0 < Wc) ? 1.f : 0.f;
    float vw1 = (w1 >= 0 && w1 < Wc) ? 1.f : 0.f;

    float w00 = (1.f - lh) * (1.f - lw) * vh0 * vw0;
    float w01 = (1.f - lh) * lw         * vh0 * vw1;
    float w10 = lh * (1.f - lw)         * vh1 * vw0;
    float w11 = lh * lw                 * vh1 * vw1;

    int ih0 = min(max(h0, 0), Hc - 1);
    int ih1 = min(max(h1, 0), Hc - 1);
    int iw0 = min(max(w0, 0), Wc - 1);
    int iw1 = min(max(w1, 0), Wc - 1);

    int i00 = ih0 * Wc + iw0;
    int i01 = ih0 * Wc + iw1;
    int i10 = ih1 * Wc + iw0;
    int i11 = ih1 * Wc + iw1;

    const float* xb = x + (size_t)b * Cc * Pc;
    float* colp = g_cols + (size_t)b * CKc * Pc + (size_t)k * Pc + p;

#pragma unroll 4
    for (int c = 0; c < Cc; ++c) {
        const float* xc = xb + (size_t)c * Pc;
        float v = w00 * xc[i00] + w01 * xc[i01] + w10 * xc[i10] + w11 * xc[i11];
        colp[(size_t)c * (Kc * Pc)] = v;
    }
}

// ---------------------------------------------------------------------------
// Stage 2: batched SGEMM  out[b] = W[256 x 2304] * cols[b][2304 x 4096]
// 128x128 tile, BK=16, 256 threads, 8x8 microtile, f32x2 packed FMA.
// ---------------------------------------------------------------------------
typedef unsigned long long ull;

__device__ __forceinline__ ull bcast2(float v) {
    ull r;
    asm("mov.b64 %0, {%1, %1};" : "=l"(r) : "f"(v));
    return r;
}
__device__ __forceinline__ ull pk2(float lo, float hi) {
    ull r;
    asm("mov.b64 %0, {%1, %2};" : "=l"(r) : "f"(lo), "f"(hi));
    return r;
}
__device__ __forceinline__ ull fma2(ull a, ull b, ull c) {
    ull d;
    asm("fma.rn.f32x2 %0, %1, %2, %3;" : "=l"(d) : "l"(a), "l"(b), "l"(c));
    return d;
}

#define BM 128
#define BN 128
#define BK 16
#define ASTRIDE 132   // padded row to kill smem bank conflicts on transposed store

__global__ __launch_bounds__(256, 2) void dcn_gemm(
    const float* __restrict__ weight,  // [OC, CK] row-major
    float* __restrict__ out)           // [B, OC, P]
{
    __shared__ __align__(16) float As[2][BK * ASTRIDE];
    __shared__ __align__(16) float Bs[2][BK * BN];

    const int tid = threadIdx.x;
    const int tx = tid & 15;        // 0..15 -> N
    const int ty = tid >> 4;        // 0..15 -> M
    const int bx = blockIdx.x;      // N tile (0..31)
    const int by = blockIdx.y;      // M tile (0..1)
    const int b  = blockIdx.z;      // batch

    const float* Ag = weight + (size_t)by * BM * CKc;
    const float* Bg = g_cols + (size_t)b * CKc * Pc + (size_t)bx * BN;

    // A staging indices: f in [0,512), am = f>>2 (row), ak4 = f&3 (float4 within BK)
    const int amA0 = (tid      ) >> 2, ak40 = (tid      ) & 3;
    const int amA1 = (tid + 256) >> 2, ak41 = (tid + 256) & 3;
    // B staging indices: f in [0,512), bk = f>>5, bn4 = f&31
    const int bk0 = (tid      ) >> 5, bn40 = (tid      ) & 31;
    const int bk1 = (tid + 256) >> 5, bn41 = (tid + 256) & 31;

    ull acc[8][4];
#pragma unroll
    for (int i = 0; i < 8; ++i)
#pragma unroll
        for (int j = 0; j < 4; ++j) acc[i][j] = 0ULL;

    // --- load tile 0 into buffer 0 ---
    {
        float4 va0 = *(const float4*)&Ag[(size_t)amA0 * CKc + 0 + ak40 * 4];
        float4 va1 = *(const float4*)&Ag[(size_t)amA1 * CKc + 0 + ak41 * 4];
        As[0][(ak40 * 4 + 0) * ASTRIDE + amA0] = va0.x;
        As[0][(ak40 * 4 + 1) * ASTRIDE + amA0] = va0.y;
        As[0][(ak40 * 4 + 2) * ASTRIDE + amA0] = va0.z;
        As[0][(ak40 * 4 + 3) * ASTRIDE + amA0] = va0.w;
        As[0][(ak41 * 4 + 0) * ASTRIDE + amA1] = va1.x;
        As[0][(ak41 * 4 + 1) * ASTRIDE + amA1] = va1.y;
        As[0][(ak41 * 4 + 2) * ASTRIDE + amA1] = va1.z;
        As[0][(ak41 * 4 + 3) * ASTRIDE + amA1] = va1.w;
        float4 vb0 = *(const float4*)&Bg[(size_t)(0 + bk0) * Pc + bn40 * 4];
        float4 vb1 = *(const float4*)&Bg[(size_t)(0 + bk1) * Pc + bn41 * 4];
        *(float4*)&Bs[0][bk0 * BN + bn40 * 4] = vb0;
        *(float4*)&Bs[0][bk1 * BN + bn41 * 4] = vb1;
    }
    __syncthreads();

    const int NT = CKc / BK;   // 144
    for (int t = 0; t < NT; ++t) {
        const int cur = t & 1, nxt = cur ^ 1;

        // prefetch next tile into registers
        float4 pa0, pa1, pb0, pb1;
        if (t + 1 < NT) {
            const int k0 = (t + 1) * BK;
            pa0 = *(const float4*)&Ag[(size_t)amA0 * CKc + k0 + ak40 * 4];
            pa1 = *(const float4*)&Ag[(size_t)amA1 * CKc + k0 + ak41 * 4];
            pb0 = *(const float4*)&Bg[(size_t)(k0 + bk0) * Pc + bn40 * 4];
            pb1 = *(const float4*)&Bg[(size_t)(k0 + bk1) * Pc + bn41 * 4];
        }

        // compute on current buffer
        const float* Ap = &As[cur][0];
        const float* Bp = &Bs[cur][0];
#pragma unroll
        for (int kk = 0; kk < BK; ++kk) {
            float4 a0 = *(const float4*)(Ap + kk * ASTRIDE + ty * 8);
            float4 a1 = *(const float4*)(Ap + kk * ASTRIDE + ty * 8 + 4);
            float4 b0 = *(const float4*)(Bp + kk * BN + tx * 8);
            float4 b1 = *(const float4*)(Bp + kk * BN + tx * 8 + 4);
            ull bb[4];
            bb[0] = pk2(b0.x, b0.y);
            bb[1] = pk2(b0.z, b0.w);
            bb[2] = pk2(b1.x, b1.y);
            bb[3] = pk2(b1.z, b1.w);
            float av[8] = {a0.x, a0.y, a0.z, a0.w, a1.x, a1.y, a1.z, a1.w};
#pragma unroll
            for (int i = 0; i < 8; ++i) {
                ull a2 = bcast2(av[i]);
#pragma unroll
                for (int j = 0; j < 4; ++j) acc[i][j] = fma2(a2, bb[j], acc[i][j]);
            }
        }

        // commit prefetched tile to the other buffer
        if (t + 1 < NT) {
            As[nxt][(ak40 * 4 + 0) * ASTRIDE + amA0] = pa0.x;
            As[nxt][(ak40 * 4 + 1) * ASTRIDE + amA0] = pa0.y;
            As[nxt][(ak40 * 4 + 2) * ASTRIDE + amA0] = pa0.z;
            As[nxt][(ak40 * 4 + 3) * ASTRIDE + amA0] = pa0.w;
            As[nxt][(ak41 * 4 + 0) * ASTRIDE + amA1] = pa1.x;
            As[nxt][(ak41 * 4 + 1) * ASTRIDE + amA1] = pa1.y;
            As[nxt][(ak41 * 4 + 2) * ASTRIDE + amA1] = pa1.z;
            As[nxt][(ak41 * 4 + 3) * ASTRIDE + amA1] = pa1.w;
            *(float4*)&Bs[nxt][bk0 * BN + bn40 * 4] = pb0;
            *(float4*)&Bs[nxt][bk1 * BN + bn41 * 4] = pb1;
        }
        __syncthreads();
    }

    // epilogue: acc[i][j] holds outputs (m = by*128+ty*8+i, n pair = bx*128+tx*8+2j)
    float* outp = out + ((size_t)b * OCc + (size_t)by * BM + ty * 8) * Pc
                      + (size_t)bx * BN + tx * 8;
#pragma unroll
    for (int i = 0; i < 8; ++i) {
#pragma unroll
        for (int j = 0; j < 4; ++j) {
            *(ull*)(outp + (size_t)i * Pc + j * 2) = acc[i][j];
        }
    }
}

// ---------------------------------------------------------------------------
extern "C" void kernel_launch(void* const* d_in, const int* in_sizes, int n_in,
                              void* d_out, int out_size) {
    const float* x      = (const float*)d_in[0];
    const float* offset = (const float*)d_in[1];
    const float* weight = (const float*)d_in[2];
    float* out = (float*)d_out;

    // Stage 1: im2col (B*K*P = 147456 threads)
    dcn_im2col<<<(Bc * Kc * Pc) / 256, 256>>>(x, offset);

    // Stage 2: batched GEMM
    dim3 grid(Pc / BN, OCc / BM, Bc);  // (32, 2, 4)
    dcn_gemm<<<grid, 256>>>(weight, out);
}

// round 3
// speedup vs baseline: 1.8743x; 1.8743x over previous
#include <cuda_runtime.h>
#include <cstdint>

// Problem constants
#define Bc   4
#define Cc   256
#define Hc   64
#define Wc   64
#define OCc  256
#define Kc   9
#define Pc   4096
#define CKc  (Cc*Kc)    // 2304

__device__ float g_cols[(size_t)Bc * CKc * Pc];

__device__ __forceinline__ uint32_t cvt_tf32(float f) {
    uint32_t r;
    asm("cvt.rna.tf32.f32 %0, %1;" : "=r"(r) : "f"(f));
    return r;
}

// ---------------------------------------------------------------------------
// Stage 1: deformable im2col — stores tf32-rounded values (RNA) so the GEMM
// can stream them straight into mma.sync without a rounding pass.
// ---------------------------------------------------------------------------
__global__ __launch_bounds__(256) void dcn_im2col(
    const float* __restrict__ x,
    const float* __restrict__ offset)
{
    int tid = blockIdx.x * 256 + threadIdx.x;
    int p = tid & (Pc - 1);
    int k = (tid >> 12) % Kc;
    int b = tid / (Pc * Kc);

    int ho = p >> 6;
    int wo = p & 63;
    int ki = k / 3;
    int kj = k - 3 * ki;

    const float* offb = offset + ((size_t)b * 18) * Pc;
    float dy = offb[(2 * k    ) * Pc + p];
    float dx = offb[(2 * k + 1) * Pc + p];

    float ph = (float)(ho - 1 + ki) + dy;
    float pw = (float)(wo - 1 + kj) + dx;

    float h0f = floorf(ph), w0f = floorf(pw);
    float lh = ph - h0f,    lw = pw - w0f;
    int h0 = (int)h0f, w0 = (int)w0f;
    int h1 = h0 + 1,   w1 = w0 + 1;

    float vh0 = (h0 >= 0 && h0 < Hc) ? 1.f : 0.f;
    float vh1 = (h1 >= 0 && h1 < Hc) ? 1.f : 0.f;
    float vw0 = (w0 >= 0 && w0 < Wc) ? 1.f : 0.f;
    float vw1 = (w1 >= 0 && w1 < Wc) ? 1.f : 0.f;

    float w00 = (1.f - lh) * (1.f - lw) * vh0 * vw0;
    float w01 = (1.f - lh) * lw         * vh0 * vw1;
    float w10 = lh * (1.f - lw)         * vh1 * vw0;
    float w11 = lh * lw                 * vh1 * vw1;

    int ih0 = min(max(h0, 0), Hc - 1);
    int ih1 = min(max(h1, 0), Hc - 1);
    int iw0 = min(max(w0, 0), Wc - 1);
    int iw1 = min(max(w1, 0), Wc - 1);

    int i00 = ih0 * Wc + iw0;
    int i01 = ih0 * Wc + iw1;
    int i10 = ih1 * Wc + iw0;
    int i11 = ih1 * Wc + iw1;

    const float* xb = x + (size_t)b * Cc * Pc;
    float* colp = g_cols + (size_t)b * CKc * Pc + (size_t)k * Pc + p;

#pragma unroll 4
    for (int c = 0; c < Cc; ++c) {
        const float* xc = xb + (size_t)c * Pc;
        float v = w00 * xc[i00] + w01 * xc[i01] + w10 * xc[i10] + w11 * xc[i11];
        colp[(size_t)c * (Kc * Pc)] = __uint_as_float(cvt_tf32(v));
    }
}

// ---------------------------------------------------------------------------
// Stage 2: tf32 mma.sync GEMM.  out[b] = W[256 x 2304] * cols[b][2304 x 4096]
// BM=256 (full OC), BN=128, BK=16. 8 warps, warp tile 64x64, m16n8k8 frags.
// 3-stage cp.async pipeline for B; A via LDG+cvt(RNA)+STS.
// ---------------------------------------------------------------------------
#define BM 256
#define BN 128
#define BK 16
#define NT (CKc / BK)    // 144
#define ASTR 20          // A smem row stride (floats), conflict-free frag loads
#define BSTR 136         // B smem row stride (floats)
#define ABUF (BM * ASTR)         // 5120 words / buffer
#define BBUF (BK * BSTR)         // 2176 words / buffer
#define SM_WORDS (3 * ABUF + 3 * BBUF)   // 21888 words = 87552 B

__device__ __forceinline__ uint32_t smem_u32(const void* p) {
    uint32_t a;
    asm("{ .reg .u64 t; cvta.to.shared.u64 t, %1; cvt.u32.u64 %0, t; }"
        : "=r"(a) : "l"(p));
    return a;
}
__device__ __forceinline__ void cp_async16(uint32_t dst, const void* src) {
    asm volatile("cp.async.cg.shared.global [%0], [%1], 16;"
                 :: "r"(dst), "l"(src) : "memory");
}
__device__ __forceinline__ void cp_commit() {
    asm volatile("cp.async.commit_group;" ::: "memory");
}
template <int N>
__device__ __forceinline__ void cp_wait() {
    asm volatile("cp.async.wait_group %0;" :: "n"(N) : "memory");
}
__device__ __forceinline__ void mma_tf32(float c[4],
                                         uint32_t a0, uint32_t a1, uint32_t a2, uint32_t a3,
                                         uint32_t b0, uint32_t b1) {
    asm volatile(
        "mma.sync.aligned.m16n8k8.row.col.f32.tf32.tf32.f32 "
        "{%0,%1,%2,%3}, {%4,%5,%6,%7}, {%8,%9}, {%0,%1,%2,%3};"
        : "+f"(c[0]), "+f"(c[1]), "+f"(c[2]), "+f"(c[3])
        : "r"(a0), "r"(a1), "r"(a2), "r"(a3), "r"(b0), "r"(b1));
}

__global__ __launch_bounds__(256, 1) void dcn_gemm_mma(
    const float* __restrict__ weight,   // [OC, CK]
    float* __restrict__ out)            // [B, OC, P]
{
    extern __shared__ float sm[];
    float* As = sm;                 // 3 x [BM][ASTR]
    float* Bs = sm + 3 * ABUF;      // 3 x [BK][BSTR]
    const uint32_t sb_B = smem_u32(Bs);

    const int tid = threadIdx.x;
    const int wid = tid >> 5;
    const int lane = tid & 31;
    const int warp_m = wid >> 1;    // 0..3  -> m offset *64
    const int warp_n = wid & 1;     // 0..1  -> n offset *64
    const int r = lane >> 2;        // 0..7
    const int c4 = lane & 3;        // 0..3

    const int bx = blockIdx.x;      // N tile (0..31)
    const int b  = blockIdx.y;      // batch

    const float* Ag = weight;                                   // full 256 rows
    const float* Bg = g_cols + (size_t)b * CKc * Pc + (size_t)bx * BN;

    // A staging: 4 float4/thread.  f = tid + i*256 -> m = f>>2, k4 = f&3
    // B staging (cp.async): 2 chunks/thread. ch = tid + j*256 -> row=ch>>5, col16=ch&31
    float acc[4][8][4];
#pragma unroll
    for (int i = 0; i < 4; ++i)
#pragma unroll
        for (int j = 0; j < 8; ++j)
#pragma unroll
            for (int q = 0; q < 4; ++q) acc[i][j][q] = 0.f;

    auto issue_B = [&](int t) {
        int buf = t % 3;
#pragma unroll
        for (int j = 0; j < 2; ++j) {
            int ch = tid + j * 256;
            int row = ch >> 5, col16 = ch & 31;
            uint32_t dst = sb_B + (uint32_t)(buf * BBUF + row * BSTR + col16 * 4) * 4u;
            cp_async16(dst, Bg + (size_t)(t * BK + row) * Pc + col16 * 4);
        }
        cp_commit();
    };
    auto load_A_regs = [&](int t, float4 pa[4]) {
#pragma unroll
        for (int i = 0; i < 4; ++i) {
            int f = tid + i * 256;
            int m = f >> 2, k4 = f & 3;
            pa[i] = *(const float4*)&Ag[(size_t)m * CKc + t * BK + k4 * 4];
        }
    };
    auto store_A = [&](int t, float4 pa[4]) {
        int buf = t % 3;
#pragma unroll
        for (int i = 0; i < 4; ++i) {
            int f = tid + i * 256;
            int m = f >> 2, k4 = f & 3;
            float4 v;
            v.x = __uint_as_float(cvt_tf32(pa[i].x));
            v.y = __uint_as_float(cvt_tf32(pa[i].y));
            v.z = __uint_as_float(cvt_tf32(pa[i].z));
            v.w = __uint_as_float(cvt_tf32(pa[i].w));
            *(float4*)&As[buf * ABUF + m * ASTR + k4 * 4] = v;
        }
    };

    // ---- prologue: tiles 0 and 1 ----
    {
        float4 pa0[4], pa1[4];
        load_A_regs(0, pa0);
        issue_B(0);
        load_A_regs(1, pa1);
        issue_B(1);
        store_A(0, pa0);
        store_A(1, pa1);
    }

    for (int t = 0; t < NT; ++t) {
        if (t + 1 < NT) cp_wait<1>(); else cp_wait<0>();
        __syncthreads();

        if (t + 2 < NT) {
            float4 pa[4];
            load_A_regs(t + 2, pa);
            issue_B(t + 2);
            store_A(t + 2, pa);
        }

        // ---- compute tile t ----
        const float* Ap = As + (t % 3) * ABUF + (warp_m * 64) * ASTR;
        const float* Bp = Bs + (t % 3) * BBUF + warp_n * 64;

#pragma unroll
        for (int kk = 0; kk < BK; kk += 8) {
            uint32_t af[4][4];
#pragma unroll
            for (int mi = 0; mi < 4; ++mi) {
                int row = mi * 16 + r;
                int col = kk + c4;
                af[mi][0] = __float_as_uint(Ap[ row      * ASTR + col    ]);
                af[mi][1] = __float_as_uint(Ap[(row + 8) * ASTR + col    ]);
                af[mi][2] = __float_as_uint(Ap[ row      * ASTR + col + 4]);
                af[mi][3] = __float_as_uint(Ap[(row + 8) * ASTR + col + 4]);
            }
            uint32_t bf[8][2];
#pragma unroll
            for (int ni = 0; ni < 8; ++ni) {
                int n = ni * 8 + r;
                bf[ni][0] = __float_as_uint(Bp[(kk + c4    ) * BSTR + n]);
                bf[ni][1] = __float_as_uint(Bp[(kk + c4 + 4) * BSTR + n]);
            }
#pragma unroll
            for (int mi = 0; mi < 4; ++mi)
#pragma unroll
                for (int ni = 0; ni < 8; ++ni)
                    mma_tf32(acc[mi][ni], af[mi][0], af[mi][1], af[mi][2], af[mi][3],
                             bf[ni][0], bf[ni][1]);
        }
    }

    // ---- epilogue: direct STG from fragments ----
    float* outb = out + (size_t)b * OCc * Pc + (size_t)bx * BN;
#pragma unroll
    for (int mi = 0; mi < 4; ++mi) {
        int oc0 = warp_m * 64 + mi * 16 + r;
#pragma unroll
        for (int ni = 0; ni < 8; ++ni) {
            int p = warp_n * 64 + ni * 8 + 2 * c4;
            float2 v0 = make_float2(acc[mi][ni][0], acc[mi][ni][1]);
            float2 v1 = make_float2(acc[mi][ni][2], acc[mi][ni][3]);
            *(float2*)(outb + (size_t) oc0      * Pc + p) = v0;
            *(float2*)(outb + (size_t)(oc0 + 8) * Pc + p) = v1;
        }
    }
}

// ---------------------------------------------------------------------------
extern "C" void kernel_launch(void* const* d_in, const int* in_sizes, int n_in,
                              void* d_out, int out_size) {
    const float* x      = (const float*)d_in[0];
    const float* offset = (const float*)d_in[1];
    const float* weight = (const float*)d_in[2];
    float* out = (float*)d_out;

    cudaFuncSetAttribute(dcn_gemm_mma,
                         cudaFuncAttributeMaxDynamicSharedMemorySize,
                         SM_WORDS * 4);

    dcn_im2col<<<(Bc * Kc * Pc) / 256, 256>>>(x, offset);

    dim3 grid(Pc / BN, Bc);   // (32, 4) = 128 CTAs
    dcn_gemm_mma<<<grid, 256, SM_WORDS * 4>>>(weight, out);
}

// round 4
// speedup vs baseline: 2.2716x; 1.2120x over previous
#include <cuda_runtime.h>
#include <cstdint>

// Problem constants
#define Bc   4
#define Cc   256
#define Hc   64
#define Wc   64
#define OCc  256
#define Kc   9
#define Pc   4096
#define CKc  (Cc*Kc)    // 2304

__device__ float g_cols[(size_t)Bc * CKc * Pc];
__device__ float g_wtf[(size_t)OCc * CKc];      // tf32-rounded weights

__device__ __forceinline__ uint32_t cvt_tf32(float f) {
    uint32_t r;
    asm("cvt.rna.tf32.f32 %0, %1;" : "=r"(r) : "f"(f));
    return r;
}

// ---------------------------------------------------------------------------
// Stage 0: round weights to tf32 (once per launch, ~5us)
// ---------------------------------------------------------------------------
__global__ __launch_bounds__(256) void round_weights(const float* __restrict__ w) {
    int i = blockIdx.x * 256 + threadIdx.x;
    if (i < OCc * CKc) g_wtf[i] = __uint_as_float(cvt_tf32(w[i]));
}

// ---------------------------------------------------------------------------
// Stage 1: deformable im2col — stores tf32-rounded values.
// ---------------------------------------------------------------------------
__global__ __launch_bounds__(256) void dcn_im2col(
    const float* __restrict__ x,
    const float* __restrict__ offset)
{
    int tid = blockIdx.x * 256 + threadIdx.x;
    int p = tid & (Pc - 1);
    int k = (tid >> 12) % Kc;
    int b = tid / (Pc * Kc);

    int ho = p >> 6;
    int wo = p & 63;
    int ki = k / 3;
    int kj = k - 3 * ki;

    const float* offb = offset + ((size_t)b * 18) * Pc;
    float dy = offb[(2 * k    ) * Pc + p];
    float dx = offb[(2 * k + 1) * Pc + p];

    float ph = (float)(ho - 1 + ki) + dy;
    float pw = (float)(wo - 1 + kj) + dx;

    float h0f = floorf(ph), w0f = floorf(pw);
    float lh = ph - h0f,    lw = pw - w0f;
    int h0 = (int)h0f, w0 = (int)w0f;
    int h1 = h0 + 1,   w1 = w0 + 1;

    float vh0 = (h0 >= 0 && h0 < Hc) ? 1.f : 0.f;
    float vh1 = (h1 >= 0 && h1 < Hc) ? 1.f : 0.f;
    float vw0 = (w0 >= 0 && w0 < Wc) ? 1.f : 0.f;
    float vw1 = (w1 >= 0 && w1 < Wc) ? 1.f : 0.f;

    float w00 = (1.f - lh) * (1.f - lw) * vh0 * vw0;
    float w01 = (1.f - lh) * lw         * vh0 * vw1;
    float w10 = lh * (1.f - lw)         * vh1 * vw0;
    float w11 = lh * lw                 * vh1 * vw1;

    int ih0 = min(max(h0, 0), Hc - 1);
    int ih1 = min(max(h1, 0), Hc - 1);
    int iw0 = min(max(w0, 0), Wc - 1);
    int iw1 = min(max(w1, 0), Wc - 1);

    int i00 = ih0 * Wc + iw0;
    int i01 = ih0 * Wc + iw1;
    int i10 = ih1 * Wc + iw0;
    int i11 = ih1 * Wc + iw1;

    const float* xb = x + (size_t)b * Cc * Pc;
    float* colp = g_cols + (size_t)b * CKc * Pc + (size_t)k * Pc + p;

#pragma unroll 4
    for (int c = 0; c < Cc; ++c) {
        const float* xc = xb + (size_t)c * Pc;
        float v = w00 * xc[i00] + w01 * xc[i01] + w10 * xc[i10] + w11 * xc[i11];
        colp[(size_t)c * (Kc * Pc)] = __uint_as_float(cvt_tf32(v));
    }
}

// ---------------------------------------------------------------------------
// Stage 2: tf32 mma.sync GEMM, full cp.async 4-stage pipeline + ldmatrix A.
// out[b] = W[256 x 2304] * cols[b][2304 x 4096]
// BM=256, BN=128, BK=16; 8 warps, warp tile 64x64.
// ---------------------------------------------------------------------------
#define BM 256
#define BN 128
#define BK 16
#define NT (CKc / BK)      // 144
#define STAGES 4
#define ASTRB 80           // A smem row stride BYTES (20 words): ldmatrix conflict-free
#define ABYTES (BM * ASTRB)          // 20480
#define BSTR 136           // B smem row stride (words)
#define BBYTES (BK * BSTR * 4)       // 8704
#define SM_TOTAL (STAGES * (ABYTES + BBYTES))   // 116736

__device__ __forceinline__ uint32_t smem_u32(const void* p) {
    uint32_t a;
    asm("{ .reg .u64 t; cvta.to.shared.u64 t, %1; cvt.u32.u64 %0, t; }"
        : "=r"(a) : "l"(p));
    return a;
}
__device__ __forceinline__ void cp_async16(uint32_t dst, const void* src) {
    asm volatile("cp.async.cg.shared.global [%0], [%1], 16;"
                 :: "r"(dst), "l"(src) : "memory");
}
__device__ __forceinline__ void cp_commit() {
    asm volatile("cp.async.commit_group;" ::: "memory");
}
template <int N>
__device__ __forceinline__ void cp_wait() {
    asm volatile("cp.async.wait_group %0;" :: "n"(N) : "memory");
}
__device__ __forceinline__ void ldmx4(uint32_t addr, uint32_t r[4]) {
    asm volatile("ldmatrix.sync.aligned.m8n8.x4.shared.b16 {%0,%1,%2,%3}, [%4];"
                 : "=r"(r[0]), "=r"(r[1]), "=r"(r[2]), "=r"(r[3]) : "r"(addr));
}
__device__ __forceinline__ void mma_tf32(float c[4],
                                         uint32_t a0, uint32_t a1, uint32_t a2, uint32_t a3,
                                         uint32_t b0, uint32_t b1) {
    asm volatile(
        "mma.sync.aligned.m16n8k8.row.col.f32.tf32.tf32.f32 "
        "{%0,%1,%2,%3}, {%4,%5,%6,%7}, {%8,%9}, {%0,%1,%2,%3};"
        : "+f"(c[0]), "+f"(c[1]), "+f"(c[2]), "+f"(c[3])
        : "r"(a0), "r"(a1), "r"(a2), "r"(a3), "r"(b0), "r"(b1));
}

__global__ __launch_bounds__(256, 1) void dcn_gemm_mma(
    float* __restrict__ out)            // [B, OC, P]
{
    extern __shared__ float sm[];
    const uint32_t sbA = smem_u32(sm);                       // STAGES x ABYTES
    const uint32_t sbB = sbA + STAGES * ABYTES;              // STAGES x BBYTES
    float* Bs = sm + (STAGES * ABYTES) / 4;

    const int tid = threadIdx.x;
    const int wid = tid >> 5;
    const int lane = tid & 31;
    const int warp_m = wid >> 1;    // 0..3
    const int warp_n = wid & 1;     // 0..1
    const int r = lane >> 2;
    const int c4 = lane & 3;

    const int bx = blockIdx.x;      // N tile (0..31)
    const int b  = blockIdx.y;      // batch

    const float* Bg = g_cols + (size_t)b * CKc * Pc + (size_t)bx * BN;

    float acc[4][8][4];
#pragma unroll
    for (int i = 0; i < 4; ++i)
#pragma unroll
        for (int j = 0; j < 8; ++j)
#pragma unroll
            for (int q = 0; q < 4; ++q) acc[i][j][q] = 0.f;

    // cp.async staging indices
    // A: 4 chunks/thread: ch = tid + i*256 -> m = ch>>2, k4 = ch&3
    // B: 2 chunks/thread: ch = tid + j*256 -> k = ch>>5, n16 = ch&31
    auto issue_tile = [&](int t) {
        const int buf = t % STAGES;
        const uint32_t abase = sbA + buf * ABYTES;
        const uint32_t bbase = sbB + buf * BBYTES;
#pragma unroll
        for (int i = 0; i < 4; ++i) {
            int ch = tid + i * 256;
            int m = ch >> 2, k4 = ch & 3;
            cp_async16(abase + (uint32_t)(m * ASTRB + k4 * 16),
                       g_wtf + (size_t)m * CKc + t * BK + k4 * 4);
        }
#pragma unroll
        for (int j = 0; j < 2; ++j) {
            int ch = tid + j * 256;
            int k = ch >> 5, n16 = ch & 31;
            cp_async16(bbase + (uint32_t)(k * (BSTR * 4) + n16 * 16),
                       Bg + (size_t)(t * BK + k) * Pc + n16 * 4);
        }
    };

    // ---- prologue: stages 0..2 ----
#pragma unroll
    for (int s = 0; s < STAGES - 1; ++s) { issue_tile(s); cp_commit(); }

    // per-lane ldmatrix base for A (within a buffer)
    const uint32_t a_lane = (uint32_t)((warp_m * 64 + (lane & 15)) * ASTRB
                                       + ((lane & 16) ? 16 : 0));

    for (int t = 0; t < NT; ++t) {
        const int buf = t % STAGES;
        cp_wait<STAGES - 2>();
        __syncthreads();

        if (t + STAGES - 1 < NT) issue_tile(t + STAGES - 1);
        cp_commit();   // always commit so wait_group counting stays exact

        const uint32_t abase = sbA + buf * ABYTES + a_lane;
        const float* Bp = Bs + buf * (BBYTES / 4) + warp_n * 64;

#pragma unroll
        for (int kk8 = 0; kk8 < 2; ++kk8) {
            uint32_t af[4][4];
#pragma unroll
            for (int mi = 0; mi < 4; ++mi)
                ldmx4(abase + (uint32_t)(mi * 16 * ASTRB + kk8 * 32), af[mi]);

            const int kk = kk8 * 8;
            uint32_t bf[8][2];
#pragma unroll
            for (int ni = 0; ni < 8; ++ni) {
                int n = ni * 8 + r;
                bf[ni][0] = __float_as_uint(Bp[(kk + c4    ) * BSTR + n]);
                bf[ni][1] = __float_as_uint(Bp[(kk + c4 + 4) * BSTR + n]);
            }
#pragma unroll
            for (int mi = 0; mi < 4; ++mi)
#pragma unroll
                for (int ni = 0; ni < 8; ++ni)
                    mma_tf32(acc[mi][ni], af[mi][0], af[mi][1], af[mi][2], af[mi][3],
                             bf[ni][0], bf[ni][1]);
        }
    }

    // ---- epilogue: direct STG from fragments ----
    float* outb = out + (size_t)b * OCc * Pc + (size_t)bx * BN;
#pragma unroll
    for (int mi = 0; mi < 4; ++mi) {
        int oc0 = warp_m * 64 + mi * 16 + r;
#pragma unroll
        for (int ni = 0; ni < 8; ++ni) {
            int p = warp_n * 64 + ni * 8 + 2 * c4;
            float2 v0 = make_float2(acc[mi][ni][0], acc[mi][ni][1]);
            float2 v1 = make_float2(acc[mi][ni][2], acc[mi][ni][3]);
            *(float2*)(outb + (size_t) oc0      * Pc + p) = v0;
            *(float2*)(outb + (size_t)(oc0 + 8) * Pc + p) = v1;
        }
    }
}

// ---------------------------------------------------------------------------
extern "C" void kernel_launch(void* const* d_in, const int* in_sizes, int n_in,
                              void* d_out, int out_size) {
    const float* x      = (const float*)d_in[0];
    const float* offset = (const float*)d_in[1];
    const float* weight = (const float*)d_in[2];
    float* out = (float*)d_out;

    cudaFuncSetAttribute(dcn_gemm_mma,
                         cudaFuncAttributeMaxDynamicSharedMemorySize, SM_TOTAL);

    round_weights<<<(OCc * CKc + 255) / 256, 256>>>(weight);
    dcn_im2col<<<(Bc * Kc * Pc) / 256, 256>>>(x, offset);

    dim3 grid(Pc / BN, Bc);   // (32, 4) = 128 CTAs
    dcn_gemm_mma<<<grid, 256, SM_TOTAL>>>(out);
}